// round 7
// baseline (speedup 1.0000x reference)
#include <cuda_runtime.h>

#define GN 100000
#define GE 1600000
#define H0 32
#define H1 8
#define SXS 132          // sX row stride in floats; 132*4=528B = 33*16 (16B-aligned rows)
#define NBLK1 391        // ceil(GN/256) scan blocks

// ---------------- scratch (static __device__ — no allocations) ----------------
__device__ __align__(16) float g_xw[GN * H0];   // x @ W0
__device__ __align__(16) float g_hw[GN * H1];   // h @ W1
__device__ int   g_cnt[GN];      // per-target edge counts
__device__ int   g_ptr[GN];      // CSR offsets (exclusive scan)
__device__ int   g_cur[GN];      // scatter cursors
__device__ int   g_bsum[512];    // scan block sums
__device__ int   g_boff[512];    // scanned block sums
__device__ int   g_src[GE];      // CSR source node per edge
__device__ float g_mwc[GE];      // masked weight, CSR order
__device__ float g_dinv1[GN];
__device__ float g_dinv2[GN];
__device__ float g_s1[GN];
__device__ float g_s2[GN];
__device__ float g_wa1[H0];
__device__ float g_wa2[H0];
__device__ float g_cbias;
__device__ int   g_is64;

// ---------------- helpers ----------------
__device__ __forceinline__ void ffma2(unsigned long long& d, unsigned long long a,
                                      unsigned long long b) {
    asm("fma.rn.f32x2 %0, %1, %2, %0;" : "+l"(d) : "l"(a), "l"(b));
}

__device__ __forceinline__ int eidx(const void* ei, long long i) {
    if (g_is64) return (int)((const long long*)ei)[i];
    return ((const int*)ei)[i];
}

// ---------------- setup: zero counts, attention collapse, dtype flag ----------------
__global__ void k_setup(const unsigned int* __restrict__ eiw,
                        const float* __restrict__ Wnb, const float* __restrict__ bnb,
                        const float* __restrict__ Wself, const float* __restrict__ bself,
                        const float* __restrict__ Watt, const float* __restrict__ batt) {
    int i = blockIdx.x * blockDim.x + threadIdx.x;
    if (i < GN) g_cnt[i] = 0;
    if (i < H0) {
        float a1 = 0.f, a2 = 0.f;
#pragma unroll
        for (int k = 0; k < 8; k++) {
            a1 += Wnb[i * 8 + k] * Watt[k];
            a2 += Wself[i * 8 + k] * Watt[8 + k];
        }
        g_wa1[i] = a1;
        g_wa2[i] = a2;
    }
    if (i == H0) {
        float c = batt[0];
        for (int k = 0; k < 8; k++) c += bnb[k] * Watt[k] + bself[k] * Watt[8 + k];
        g_cbias = c;
    }
    if (i == H0 + 1) {
        // edge values < 2^17: if int64 (LE), every odd 32-bit word is 0
        int all0 = 1;
        for (int j = 1; j < 512; j += 2)
            if (eiw[j] != 0u) { all0 = 0; break; }
        g_is64 = all0;
    }
}

// ---------------- GEMM: xw = x @ W0  (100000 x 512 x 32) ----------------
// 128 rows x 32 cols per block, 128 threads; thread = 16 rows x 2 cols (f32x2 accs).
// sX transposed + XOR swizzle rs = r ^ 4q (conflict-free stores, aligned 16B loads).
__global__ __launch_bounds__(128, 5) void k_gemm(const float* __restrict__ x,
                                                 const float* __restrict__ W0) {
    __shared__ __align__(16) float  sX[32 * SXS];   // 16.9KB
    __shared__ __align__(16) float2 sW[32 * 32];    // 8KB

    const int tid = threadIdx.x;
    const int rg = tid >> 4;       // 0..7
    const int cg = tid & 15;       // cols 2cg, 2cg+1
    const int rbase = blockIdx.x * 128;

    unsigned long long acc[8][2];
#pragma unroll
    for (int p = 0; p < 8; p++) { acc[p][0] = 0ull; acc[p][1] = 0ull; }

    for (int k0 = 0; k0 < 512; k0 += 32) {
#pragma unroll
        for (int i = 0; i < 8; i++) {
            int idx = tid + 128 * i;
            int kk = idx >> 5, cc = idx & 31;
            float w = W0[(k0 + kk) * H0 + cc];
            sW[kk * 32 + cc] = make_float2(w, w);
        }
#pragma unroll
        for (int i = 0; i < 8; i++) {
            int idx = tid + 128 * i;
            int r = idx >> 3;          // 0..127
            int q = idx & 7;
            int grow = rbase + r;
            if (grow >= GN) grow = GN - 1;
            float4 v = *reinterpret_cast<const float4*>(
                x + (size_t)grow * 512 + k0 + 4 * q);
            int rs = r ^ (4 * q);
            sX[(4 * q + 0) * SXS + rs] = v.x;
            sX[(4 * q + 1) * SXS + rs] = v.y;
            sX[(4 * q + 2) * SXS + rs] = v.z;
            sX[(4 * q + 3) * SXS + rs] = v.w;
        }
        __syncthreads();

#pragma unroll
        for (int kk = 0; kk < 32; kk++) {
            ulonglong2 wv = *reinterpret_cast<const ulonglong2*>(&sW[kk * 32 + 2 * cg]);
            const int f = ((kk >> 2) & 7) << 2;
#pragma unroll
            for (int t = 0; t < 4; t++) {
                ulonglong2 xv = *reinterpret_cast<const ulonglong2*>(
                    &sX[kk * SXS + ((rg * 16 + 4 * t) ^ f)]);
                ffma2(acc[2 * t + 0][0], xv.x, wv.x);
                ffma2(acc[2 * t + 0][1], xv.x, wv.y);
                ffma2(acc[2 * t + 1][0], xv.y, wv.x);
                ffma2(acc[2 * t + 1][1], xv.y, wv.y);
            }
        }
        __syncthreads();
    }

#pragma unroll
    for (int p = 0; p < 8; p++) {
        float lo0 = __uint_as_float((unsigned)(acc[p][0] & 0xFFFFFFFFull));
        float hi0 = __uint_as_float((unsigned)(acc[p][0] >> 32));
        float lo1 = __uint_as_float((unsigned)(acc[p][1] & 0xFFFFFFFFull));
        float hi1 = __uint_as_float((unsigned)(acc[p][1] >> 32));
        int r = rbase + rg * 16 + 2 * p;
        if (r < GN)
            *reinterpret_cast<float2*>(&g_xw[r * H0 + 2 * cg]) = make_float2(lo0, lo1);
        if (r + 1 < GN)
            *reinterpret_cast<float2*>(&g_xw[(r + 1) * H0 + 2 * cg]) = make_float2(hi0, hi1);
    }
}

// ---------------- CSR build ----------------
__global__ void k_deg(const void* __restrict__ ei) {
    int e = blockIdx.x * blockDim.x + threadIdx.x;
    if (e >= GE) return;
    atomicAdd(&g_cnt[eidx(ei, (long long)GE + e)], 1);
}

__global__ void k_scan1() {
    __shared__ int sh[256];
    int tid = threadIdx.x;
    int i = blockIdx.x * 256 + tid;
    int v = (i < GN) ? g_cnt[i] : 0;
    sh[tid] = v;
    __syncthreads();
    for (int off = 1; off < 256; off <<= 1) {
        int t = (tid >= off) ? sh[tid - off] : 0;
        __syncthreads();
        sh[tid] += t;
        __syncthreads();
    }
    if (i < GN) g_ptr[i] = sh[tid] - v;      // exclusive within block
    if (tid == 255) g_bsum[blockIdx.x] = sh[255];
}

__global__ void k_scan2() {
    __shared__ int sh[512];
    int tid = threadIdx.x;
    int v = (tid < NBLK1) ? g_bsum[tid] : 0;
    sh[tid] = v;
    __syncthreads();
    for (int off = 1; off < 512; off <<= 1) {
        int t = (tid >= off) ? sh[tid - off] : 0;
        __syncthreads();
        sh[tid] += t;
        __syncthreads();
    }
    g_boff[tid] = sh[tid] - v;               // exclusive
}

__global__ void k_scan3() {
    int i = blockIdx.x * blockDim.x + threadIdx.x;
    if (i >= GN) return;
    int p = g_ptr[i] + g_boff[i >> 8];
    g_ptr[i] = p;
    g_cur[i] = p;
    g_dinv1[i] = rsqrtf(1.0f + (float)g_cnt[i]);  // +1 self-loop
}

__global__ void k_scatter(const void* __restrict__ ei) {
    int e = blockIdx.x * blockDim.x + threadIdx.x;
    if (e >= GE) return;
    int r = eidx(ei, e);
    int c = eidx(ei, (long long)GE + e);
    int pos = atomicAdd(&g_cur[c], 1);
    g_src[pos] = r;
}

// ---------------- conv1 aggregation + node phase (warp per target node) ----------------
// h = dinv1[n]*Σ_src xw[src]*dinv1[src] + xw[n]*dinv1[n]^2 + b0 ; then s1,s2,hw.
__global__ __launch_bounds__(256) void k_agg1n(const float* __restrict__ b0,
                                               const float* __restrict__ W1) {
    int node = blockIdx.x * 8 + (threadIdx.x >> 5);
    int lane = threadIdx.x & 31;
    if (node >= GN) return;

    int beg = g_ptr[node];
    int cnt = g_cnt[node];
    float dn = g_dinv1[node];

    float acc = 0.f;
    for (int base = 0; base < cnt; base += 32) {
        int n = min(32, cnt - base);
        int src = 0;
        float ds = 0.f;
        if (lane < n) {
            src = g_src[beg + base + lane];
            ds = g_dinv1[src];
        }
        for (int j = 0; j < n; j++) {
            int s = __shfl_sync(0xFFFFFFFFu, src, j);
            float w = __shfl_sync(0xFFFFFFFFu, ds, j);
            acc += g_xw[s * H0 + lane] * w;
        }
    }
    float h = acc * dn + g_xw[node * H0 + lane] * dn * dn + b0[lane];

    float p1 = h * g_wa1[lane];
    float p2 = h * g_wa2[lane];
#pragma unroll
    for (int o = 16; o; o >>= 1) {
        p1 += __shfl_xor_sync(0xFFFFFFFFu, p1, o);
        p2 += __shfl_xor_sync(0xFFFFFFFFu, p2, o);
    }
    if (lane == 0) { g_s1[node] = p1; g_s2[node] = p2; }

    float4 wA = *reinterpret_cast<const float4*>(W1 + lane * 8);
    float4 wB = *reinterpret_cast<const float4*>(W1 + lane * 8 + 4);
    float o0 = h * wA.x, o1 = h * wA.y, o2 = h * wA.z, o3 = h * wA.w;
    float o4 = h * wB.x, o5 = h * wB.y, o6 = h * wB.z, o7 = h * wB.w;
#pragma unroll
    for (int o = 16; o; o >>= 1) {
        o0 += __shfl_xor_sync(0xFFFFFFFFu, o0, o);
        o1 += __shfl_xor_sync(0xFFFFFFFFu, o1, o);
        o2 += __shfl_xor_sync(0xFFFFFFFFu, o2, o);
        o3 += __shfl_xor_sync(0xFFFFFFFFu, o3, o);
        o4 += __shfl_xor_sync(0xFFFFFFFFu, o4, o);
        o5 += __shfl_xor_sync(0xFFFFFFFFu, o5, o);
        o6 += __shfl_xor_sync(0xFFFFFFFFu, o6, o);
        o7 += __shfl_xor_sync(0xFFFFFFFFu, o7, o);
    }
    if (lane == 0) {
        float4* hw4 = reinterpret_cast<float4*>(&g_hw[node * H1]);
        hw4[0] = make_float4(o0, o1, o2, o3);
        hw4[1] = make_float4(o4, o5, o6, o7);
    }
}

// ---------------- gate: per-node segment, mw in CSR order, dinv2 (no atomics) ----------
__global__ void k_gate() {
    int node = blockIdx.x * blockDim.x + threadIdx.x;
    if (node >= GN) return;
    int beg = g_ptr[node];
    int cnt = g_cnt[node];
    float s2v = g_s2[node] + g_cbias;
    float dacc = 1.0f;   // self-loop weight
    for (int j = 0; j < cnt; j++) {
        float w = g_s1[g_src[beg + j]] + s2v;
        float mw = 0.f;
        if (w > 0.f) {
            float s = 1.f / (1.f + __expf(-w));
            mw = fminf(s * 1.01f, 1.f) * w;
            dacc += mw;
        }
        g_mwc[beg + j] = mw;
    }
    g_dinv2[node] = rsqrtf(dacc);
}

// ---------------- conv2 aggregation: warp per node, lanes 0..7 = features ------------
__global__ __launch_bounds__(256) void k_agg2(float* __restrict__ out,
                                              const float* __restrict__ b1) {
    int node = blockIdx.x * 8 + (threadIdx.x >> 5);
    int lane = threadIdx.x & 31;
    if (node >= GN) return;

    int beg = g_ptr[node];
    int cnt = g_cnt[node];
    float dn = g_dinv2[node];

    float acc = 0.f;
    for (int base = 0; base < cnt; base += 32) {
        int n = min(32, cnt - base);
        float c = 0.f;
        int src = 0;
        if (lane < n) {
            src = g_src[beg + base + lane];
            c = g_mwc[beg + base + lane] * g_dinv2[src];
        }
        for (int j = 0; j < n; j++) {
            int s = __shfl_sync(0xFFFFFFFFu, src, j);
            float cj = __shfl_sync(0xFFFFFFFFu, c, j);
            if (lane < 8 && cj != 0.f) acc += g_hw[s * H1 + lane] * cj;
        }
    }
    if (lane < 8)
        out[node * H1 + lane] = acc * dn + g_hw[node * H1 + lane] * dn * dn + b1[lane];
}

// ---------------- launch ----------------
extern "C" void kernel_launch(void* const* d_in, const int* in_sizes, int n_in,
                              void* d_out, int out_size) {
    const float* x   = (const float*)d_in[0];
    const void*  ei  = d_in[1];
    const float* W0  = (const float*)d_in[2];
    const float* b0  = (const float*)d_in[3];
    const float* W1  = (const float*)d_in[4];
    const float* b1  = (const float*)d_in[5];
    const float* Wnb = (const float*)d_in[6];
    const float* bnb = (const float*)d_in[7];
    const float* Wself = (const float*)d_in[8];
    const float* bself = (const float*)d_in[9];
    const float* Watt  = (const float*)d_in[10];
    const float* batt  = (const float*)d_in[11];
    float* out = (float*)d_out;

    k_setup<<<NBLK1, 256>>>((const unsigned int*)ei, Wnb, bnb, Wself, bself, Watt, batt);
    k_deg<<<(GE + 255) / 256, 256>>>(ei);
    k_scan1<<<NBLK1, 256>>>();
    k_scan2<<<1, 512>>>();
    k_scan3<<<NBLK1, 256>>>();
    k_scatter<<<(GE + 255) / 256, 256>>>(ei);
    k_gemm<<<(GN + 127) / 128, 128>>>(x, W0);
    k_agg1n<<<(GN + 7) / 8, 256>>>(b0, W1);
    k_gate<<<NBLK1, 256>>>();
    k_agg2<<<(GN + 7) / 8, 256>>>(out, b1);
}

// round 8
// speedup vs baseline: 1.1640x; 1.1640x over previous
#include <cuda_runtime.h>

#define GN 100000
#define GE 1600000
#define H0 32
#define H1 8
#define SXS 260   // sX row stride in floats; 16B-aligned rows, conflict-free with rs=r^4q

// ---------------- scratch (static __device__ — no allocations) ----------------
__device__ __align__(16) float g_xw[GN * H0];    // x @ W0
__device__ __align__(16) float g_hacc[GN * H0];  // conv1 edge aggregation
__device__ __align__(16) float g_out[GN * H1];   // conv2 aggregation (no atomics on d_out)
__device__ __align__(16) float g_hw[GN * H1];    // h @ W1
__device__ float g_deg1[GN];       // deg1 -> dinv1 (in place)
__device__ float g_deg2[GN];       // deg2 -> dinv2 (in place)
__device__ float g_s1[GN];
__device__ float g_s2[GN];
__device__ float g_mw[GE];         // masked edge weight
__device__ float g_wa1[H0];
__device__ float g_wa2[H0];
__device__ float g_cbias;
__device__ int   g_is64;

// ---------------- helpers ----------------
__device__ __forceinline__ void ffma2(unsigned long long& d, unsigned long long a,
                                      unsigned long long b) {
    asm("fma.rn.f32x2 %0, %1, %2, %0;" : "+l"(d) : "l"(a), "l"(b));
}

__device__ __forceinline__ void red4(float* a, float x, float y, float z, float w) {
    asm volatile(
        "{\n\t"
        ".reg .u64 p;\n\t"
        "cvta.to.global.u64 p, %0;\n\t"
        "red.global.add.v4.f32 [p], {%1,%2,%3,%4};\n\t"
        "}"
        :: "l"(a), "f"(x), "f"(y), "f"(z), "f"(w) : "memory");
}

__device__ __forceinline__ int eidx(const void* ei, long long i) {
    if (g_is64) return (int)((const long long*)ei)[i];
    return ((const int*)ei)[i];
}

// ---------------- fused setup: zero hacc, degs=1, wa1/wa2/cbias, dtype flag --------
__global__ void k_setup(const unsigned int* __restrict__ eiw,
                        const float* __restrict__ Wnb, const float* __restrict__ bnb,
                        const float* __restrict__ Wself, const float* __restrict__ bself,
                        const float* __restrict__ Watt, const float* __restrict__ batt) {
    int i = blockIdx.x * blockDim.x + threadIdx.x;
    if (i < GN * H0) g_hacc[i] = 0.f;
    if (i < GN) { g_deg1[i] = 1.f; g_deg2[i] = 1.f; }  // self-loop weight 1
    if (i < H0) {
        float a1 = 0.f, a2 = 0.f;
#pragma unroll
        for (int k = 0; k < 8; k++) {
            a1 += Wnb[i * 8 + k] * Watt[k];
            a2 += Wself[i * 8 + k] * Watt[8 + k];
        }
        g_wa1[i] = a1;
        g_wa2[i] = a2;
    }
    if (i == H0) {
        float c = batt[0];
        for (int k = 0; k < 8; k++) c += bnb[k] * Watt[k] + bself[k] * Watt[8 + k];
        g_cbias = c;
    }
    if (i == H0 + 1) {
        // edge values < 2^17: if int64 (LE), every odd 32-bit word is 0
        int all0 = 1;
        for (int j = 1; j < 512; j += 2)
            if (eiw[j] != 0u) { all0 = 0; break; }
        g_is64 = all0;
    }
}

// ---------------- GEMM: xw = x @ W0  (100000 x 512 x 32) ----------------
// 256 rows x 32 cols per block, 128 threads; thread = 32 rows x 2 cols (f32x2 accs).
// Per warp*kk: 32 FFMA2 vs 10 LDS wavefronts -> FMA-bound at 12 warps/SM.
__global__ __launch_bounds__(128, 3) void k_gemm(const float* __restrict__ x,
                                                 const float* __restrict__ W0) {
    __shared__ __align__(16) float  sX[32 * SXS];   // 33.3KB
    __shared__ __align__(16) float2 sW[32 * 32];    // 8KB

    const int tid = threadIdx.x;
    const int rg = tid >> 4;       // 0..7 -> rows rg*32 .. rg*32+31
    const int cg = tid & 15;       // cols 2cg, 2cg+1
    const int rbase = blockIdx.x * 256;

    unsigned long long acc[16][2];
#pragma unroll
    for (int p = 0; p < 16; p++) { acc[p][0] = 0ull; acc[p][1] = 0ull; }

    for (int k0 = 0; k0 < 512; k0 += 32) {
        // stage W chunk (32x32): 8 floats/thread, dup into float2
#pragma unroll
        for (int i = 0; i < 8; i++) {
            int idx = tid + 128 * i;
            int kk = idx >> 5, cc = idx & 31;
            float w = W0[(k0 + kk) * H0 + cc];
            sW[kk * 32 + cc] = make_float2(w, w);
        }
        // stage x chunk (256 rows x 32 k), transposed + swizzled: 16 float4/thread
#pragma unroll
        for (int i = 0; i < 16; i++) {
            int idx = tid + 128 * i;
            int r = idx >> 3;          // 0..255
            int q = idx & 7;           // k-group
            int grow = rbase + r;
            if (grow >= GN) grow = GN - 1;
            float4 v = *reinterpret_cast<const float4*>(
                x + (size_t)grow * 512 + k0 + 4 * q);
            int rs = r ^ (4 * q);
            sX[(4 * q + 0) * SXS + rs] = v.x;
            sX[(4 * q + 1) * SXS + rs] = v.y;
            sX[(4 * q + 2) * SXS + rs] = v.z;
            sX[(4 * q + 3) * SXS + rs] = v.w;
        }
        __syncthreads();

#pragma unroll
        for (int kk = 0; kk < 32; kk++) {
            ulonglong2 wv = *reinterpret_cast<const ulonglong2*>(&sW[kk * 32 + 2 * cg]);
            const int f = ((kk >> 2) & 7) << 2;
#pragma unroll
            for (int t = 0; t < 8; t++) {
                ulonglong2 xv = *reinterpret_cast<const ulonglong2*>(
                    &sX[kk * SXS + ((rg * 32 + 4 * t) ^ f)]);
                ffma2(acc[2 * t + 0][0], xv.x, wv.x);
                ffma2(acc[2 * t + 0][1], xv.x, wv.y);
                ffma2(acc[2 * t + 1][0], xv.y, wv.x);
                ffma2(acc[2 * t + 1][1], xv.y, wv.y);
            }
        }
        __syncthreads();
    }

#pragma unroll
    for (int p = 0; p < 16; p++) {
        float lo0 = __uint_as_float((unsigned)(acc[p][0] & 0xFFFFFFFFull));
        float hi0 = __uint_as_float((unsigned)(acc[p][0] >> 32));
        float lo1 = __uint_as_float((unsigned)(acc[p][1] & 0xFFFFFFFFull));
        float hi1 = __uint_as_float((unsigned)(acc[p][1] >> 32));
        int r = rbase + rg * 32 + 2 * p;
        if (r < GN)
            *reinterpret_cast<float2*>(&g_xw[r * H0 + 2 * cg]) = make_float2(lo0, lo1);
        if (r + 1 < GN)
            *reinterpret_cast<float2*>(&g_xw[(r + 1) * H0 + 2 * cg]) = make_float2(hi0, hi1);
    }
}

// ---------------- degree for conv1 ----------------
__global__ void k_deg1(const void* __restrict__ ei) {
    int e = blockIdx.x * blockDim.x + threadIdx.x;
    if (e >= GE) return;
    atomicAdd(&g_deg1[eidx(ei, (long long)GE + e)], 1.0f);
}

__global__ void k_rsq1() {
    int i = blockIdx.x * blockDim.x + threadIdx.x;
    if (i < GN) g_deg1[i] = rsqrtf(g_deg1[i]);
}

// ---------------- conv1 aggregation: 8 threads / edge, RED.128 ----------------
__global__ void k_agg1(const void* __restrict__ ei) {
    long long t = (long long)blockIdx.x * blockDim.x + threadIdx.x;
    if (t >= (long long)GE * 8) return;
    int e = (int)(t >> 3), q = (int)(t & 7);
    int row = eidx(ei, e);
    int col = eidx(ei, (long long)GE + e);
    float norm = g_deg1[row] * g_deg1[col];  // dinv1 in place
    float4 v = *reinterpret_cast<const float4*>(&g_xw[row * H0 + q * 4]);
    red4(&g_hacc[col * H0 + q * 4], v.x * norm, v.y * norm, v.z * norm, v.w * norm);
}

// ---------------- per-node: h, s1, s2, hw = h @ W1 (warp per node) ----------------
__global__ void k_node(const float* __restrict__ b0, const float* __restrict__ W1) {
    int node = (blockIdx.x * blockDim.x + threadIdx.x) >> 5;
    int lane = threadIdx.x & 31;
    if (node >= GN) return;

    float di = g_deg1[node];  // dinv1
    float h = g_hacc[node * H0 + lane] + g_xw[node * H0 + lane] * di * di + b0[lane];

    float p1 = h * g_wa1[lane];
    float p2 = h * g_wa2[lane];
#pragma unroll
    for (int o = 16; o; o >>= 1) {
        p1 += __shfl_xor_sync(0xFFFFFFFFu, p1, o);
        p2 += __shfl_xor_sync(0xFFFFFFFFu, p2, o);
    }
    if (lane == 0) { g_s1[node] = p1; g_s2[node] = p2; }

    float4 wA = *reinterpret_cast<const float4*>(W1 + lane * 8);
    float4 wB = *reinterpret_cast<const float4*>(W1 + lane * 8 + 4);
    float o0 = h * wA.x, o1 = h * wA.y, o2 = h * wA.z, o3 = h * wA.w;
    float o4 = h * wB.x, o5 = h * wB.y, o6 = h * wB.z, o7 = h * wB.w;
#pragma unroll
    for (int o = 16; o; o >>= 1) {
        o0 += __shfl_xor_sync(0xFFFFFFFFu, o0, o);
        o1 += __shfl_xor_sync(0xFFFFFFFFu, o1, o);
        o2 += __shfl_xor_sync(0xFFFFFFFFu, o2, o);
        o3 += __shfl_xor_sync(0xFFFFFFFFu, o3, o);
        o4 += __shfl_xor_sync(0xFFFFFFFFu, o4, o);
        o5 += __shfl_xor_sync(0xFFFFFFFFu, o5, o);
        o6 += __shfl_xor_sync(0xFFFFFFFFu, o6, o);
        o7 += __shfl_xor_sync(0xFFFFFFFFu, o7, o);
    }
    if (lane == 0) {
        float4* hw4 = reinterpret_cast<float4*>(&g_hw[node * H1]);
        hw4[0] = make_float4(o0, o1, o2, o3);
        hw4[1] = make_float4(o4, o5, o6, o7);
    }
}

// ---------------- edge gate + deg2 ----------------
__global__ void k_gate(const void* __restrict__ ei) {
    int e = blockIdx.x * blockDim.x + threadIdx.x;
    if (e >= GE) return;
    int row = eidx(ei, e);
    int col = eidx(ei, (long long)GE + e);
    float w = g_s1[row] + g_s2[col] + g_cbias;  // pre-relu attention logit
    float mw = 0.f;
    if (w > 0.f) {
        float s = 1.f / (1.f + __expf(-w));       // sigmoid(relu(w)), w>0
        float mask = fminf(s * 1.01f, 1.f);       // clip(s*(zeta-gamma)+gamma, 0, 1)
        mw = mask * w;
        atomicAdd(&g_deg2[col], mw);
    }
    g_mw[e] = mw;
}

// ---------------- rsq2 + g_out init (thread per node) ----------------
__global__ void k_oinit(const float* __restrict__ b1) {
    int node = blockIdx.x * blockDim.x + threadIdx.x;
    if (node >= GN) return;
    float d = rsqrtf(g_deg2[node]);
    g_deg2[node] = d;           // dinv2 for agg2
    float dd = d * d;
    float4 hw0 = *reinterpret_cast<const float4*>(&g_hw[node * H1]);
    float4 hw1 = *reinterpret_cast<const float4*>(&g_hw[node * H1 + 4]);
    float4 bA = *reinterpret_cast<const float4*>(b1);
    float4 bB = *reinterpret_cast<const float4*>(b1 + 4);
    float4 o0 = make_float4(hw0.x * dd + bA.x, hw0.y * dd + bA.y,
                            hw0.z * dd + bA.z, hw0.w * dd + bA.w);
    float4 o1 = make_float4(hw1.x * dd + bB.x, hw1.y * dd + bB.y,
                            hw1.z * dd + bB.z, hw1.w * dd + bB.w);
    *reinterpret_cast<float4*>(&g_out[node * H1]) = o0;
    *reinterpret_cast<float4*>(&g_out[node * H1 + 4]) = o1;
}

// ---------------- conv2 aggregation: 2 threads / edge, RED.128 ----------------
__global__ void k_agg2(const void* __restrict__ ei) {
    long long t = (long long)blockIdx.x * blockDim.x + threadIdx.x;
    if (t >= (long long)GE * 2) return;
    int e = (int)(t >> 1), q = (int)(t & 1);
    float mw = g_mw[e];
    if (mw == 0.f) return;  // gated off: exact zero contribution
    int row = eidx(ei, e);
    int col = eidx(ei, (long long)GE + e);
    float norm = g_deg2[row] * mw * g_deg2[col];
    float4 v = *reinterpret_cast<const float4*>(&g_hw[row * H1 + q * 4]);
    red4(&g_out[col * H1 + q * 4], v.x * norm, v.y * norm, v.z * norm, v.w * norm);
}

// ---------------- final copy: plain stores to harness buffer ----------------
__global__ void k_final(float* __restrict__ out) {
    int i = blockIdx.x * blockDim.x + threadIdx.x;
    if (i < GN * H1 / 4) {
        reinterpret_cast<float4*>(out)[i] = reinterpret_cast<const float4*>(g_out)[i];
    }
}

// ---------------- launch ----------------
extern "C" void kernel_launch(void* const* d_in, const int* in_sizes, int n_in,
                              void* d_out, int out_size) {
    const float* x   = (const float*)d_in[0];
    const void*  ei  = d_in[1];
    const float* W0  = (const float*)d_in[2];
    const float* b0  = (const float*)d_in[3];
    const float* W1  = (const float*)d_in[4];
    const float* b1  = (const float*)d_in[5];
    const float* Wnb = (const float*)d_in[6];
    const float* bnb = (const float*)d_in[7];
    const float* Wself = (const float*)d_in[8];
    const float* bself = (const float*)d_in[9];
    const float* Watt  = (const float*)d_in[10];
    const float* batt  = (const float*)d_in[11];
    float* out = (float*)d_out;

    k_setup<<<(GN * H0 + 255) / 256, 256>>>((const unsigned int*)ei,
                                            Wnb, bnb, Wself, bself, Watt, batt);
    k_gemm<<<(GN + 255) / 256, 128>>>(x, W0);
    k_deg1<<<(GE + 255) / 256, 256>>>(ei);
    k_rsq1<<<(GN + 255) / 256, 256>>>();
    k_agg1<<<(GE * 8 + 255) / 256, 256>>>(ei);
    k_node<<<(GN * 32 + 255) / 256, 256>>>(b0, W1);
    k_gate<<<(GE + 255) / 256, 256>>>(ei);
    k_oinit<<<(GN + 255) / 256, 256>>>(b1);
    k_agg2<<<(GE * 2 + 255) / 256, 256>>>(ei);
    k_final<<<(GN * H1 / 4 + 255) / 256, 256>>>(out);
}

// round 10
// speedup vs baseline: 1.4300x; 1.2285x over previous
#include <cuda_runtime.h>
#include <cstdint>

#define GN 100000
#define GE 1600000
#define H0 32
#define H1 8

// ---------------- scratch (static __device__ — no allocations) ----------------
__device__ __align__(16) float g_xw[GN * H0];    // x @ W0
__device__ __align__(16) float g_hacc[GN * H0];  // conv1 edge aggregation
__device__ __align__(16) float g_out[GN * H1];   // conv2 aggregation (no atomics on d_out)
__device__ __align__(16) float g_hw[GN * H1];    // h @ W1
__device__ float g_deg1[GN];       // raw degree (1 + count)
__device__ float g_deg2[GN];       // masked-weight degree -> dinv2 (in place)
__device__ float g_s1[GN];
__device__ float g_s2[GN];
__device__ float g_mw[GE];         // masked edge weight
__device__ float g_wa1[H0];
__device__ float g_wa2[H0];
__device__ float g_cbias;
__device__ int   g_is64;

// ---------------- helpers ----------------
__device__ __forceinline__ void red4(float* a, float x, float y, float z, float w) {
    asm volatile(
        "{\n\t"
        ".reg .u64 p;\n\t"
        "cvta.to.global.u64 p, %0;\n\t"
        "red.global.add.v4.f32 [p], {%1,%2,%3,%4};\n\t"
        "}"
        :: "l"(a), "f"(x), "f"(y), "f"(z), "f"(w) : "memory");
}

__device__ __forceinline__ int eidx(const void* ei, long long i) {
    if (g_is64) return (int)((const long long*)ei)[i];
    return ((const int*)ei)[i];
}

__device__ __forceinline__ float tf32r(float a) {
    float r;
    asm("cvt.rna.tf32.f32 %0, %1;" : "=f"(r) : "f"(a));
    return r;
}

__device__ __forceinline__ void mma_tf32(float* c, uint32_t a0, uint32_t a1,
                                         uint32_t a2, uint32_t a3,
                                         uint32_t b0, uint32_t b1) {
    asm("mma.sync.aligned.m16n8k8.row.col.f32.tf32.tf32.f32 "
        "{%0,%1,%2,%3},{%4,%5,%6,%7},{%8,%9},{%0,%1,%2,%3};"
        : "+f"(c[0]), "+f"(c[1]), "+f"(c[2]), "+f"(c[3])
        : "r"(a0), "r"(a1), "r"(a2), "r"(a3), "r"(b0), "r"(b1));
}

// ---------------- fused setup ----------------
__global__ void k_setup(const unsigned int* __restrict__ eiw,
                        const float* __restrict__ Wnb, const float* __restrict__ bnb,
                        const float* __restrict__ Wself, const float* __restrict__ bself,
                        const float* __restrict__ Watt, const float* __restrict__ batt) {
    int i = blockIdx.x * blockDim.x + threadIdx.x;
    if (i < GN * H0) g_hacc[i] = 0.f;
    if (i < GN) { g_deg1[i] = 1.f; g_deg2[i] = 1.f; }  // self-loop weight 1
    if (i < H0) {
        float a1 = 0.f, a2 = 0.f;
#pragma unroll
        for (int k = 0; k < 8; k++) {
            a1 += Wnb[i * 8 + k] * Watt[k];
            a2 += Wself[i * 8 + k] * Watt[8 + k];
        }
        g_wa1[i] = a1;
        g_wa2[i] = a2;
    }
    if (i == H0) {
        float c = batt[0];
        for (int k = 0; k < 8; k++) c += bnb[k] * Watt[k] + bself[k] * Watt[8 + k];
        g_cbias = c;
    }
    if (i == H0 + 1) {
        // edge values < 2^17: if int64 (LE), every odd 32-bit word is 0
        int all0 = 1;
        for (int j = 1; j < 512; j += 2)
            if (eiw[j] != 0u) { all0 = 0; break; }
        g_is64 = all0;
    }
}

// ---------------- GEMM: xw = x @ W0, tf32 tensor cores ----------------
// Block: 128 threads (4 warps), 256 rows x 32 cols. Warp: 64 rows (4 m16 tiles),
// N=32 (4 n8 tiles). K chunk 32 (4 k8 steps). DRAM-bound on x (205 MB).
#define SXP 36   // sX row stride: (4*g+tg) mod 32 distinct -> conflict-free A frags
#define SWP 33
__global__ __launch_bounds__(128) void k_gemm(const float* __restrict__ x,
                                              const float* __restrict__ W0) {
    __shared__ __align__(16) float sX[256 * SXP];  // 36.9KB (tf32-rounded values)
    __shared__ __align__(16) float sW[32 * SWP];   // 4.2KB

    const int tid = threadIdx.x;
    const int lane = tid & 31;
    const int gid = lane >> 2;     // group id 0..7
    const int tg = lane & 3;       // thread-in-group 0..3
    const int mbase = (tid >> 5) * 64;  // warp row offset in block
    const int rbase = blockIdx.x * 256;

    float c[4][4][4];
#pragma unroll
    for (int mt = 0; mt < 4; mt++)
#pragma unroll
        for (int t = 0; t < 4; t++)
#pragma unroll
            for (int r = 0; r < 4; r++) c[mt][t][r] = 0.f;

    for (int k0 = 0; k0 < 512; k0 += 32) {
        // stage x: 256 rows x 32 cols, 16 float4/thread, tf32-rounded
#pragma unroll
        for (int i = 0; i < 16; i++) {
            int idx = tid + 128 * i;
            int row = idx >> 3, q = idx & 7;
            int grow = rbase + row;
            if (grow >= GN) grow = GN - 1;
            float4 v = *reinterpret_cast<const float4*>(
                x + (size_t)grow * 512 + k0 + 4 * q);
            v.x = tf32r(v.x); v.y = tf32r(v.y); v.z = tf32r(v.z); v.w = tf32r(v.w);
            *reinterpret_cast<float4*>(&sX[row * SXP + 4 * q]) = v;
        }
        // stage W chunk (32x32), 8 floats/thread
#pragma unroll
        for (int i = 0; i < 8; i++) {
            int idx = tid + 128 * i;
            int kk = idx >> 5, cc = idx & 31;
            sW[kk * SWP + cc] = tf32r(W0[(k0 + kk) * H0 + cc]);
        }
        __syncthreads();

#pragma unroll
        for (int kk = 0; kk < 4; kk++) {
            uint32_t b[4][2];
#pragma unroll
            for (int t = 0; t < 4; t++) {
                b[t][0] = __float_as_uint(sW[(kk * 8 + tg) * SWP + t * 8 + gid]);
                b[t][1] = __float_as_uint(sW[(kk * 8 + tg + 4) * SWP + t * 8 + gid]);
            }
#pragma unroll
            for (int mt = 0; mt < 4; mt++) {
                int r0 = mbase + mt * 16;
                uint32_t a0 = __float_as_uint(sX[(r0 + gid) * SXP + kk * 8 + tg]);
                uint32_t a1 = __float_as_uint(sX[(r0 + gid + 8) * SXP + kk * 8 + tg]);
                uint32_t a2 = __float_as_uint(sX[(r0 + gid) * SXP + kk * 8 + tg + 4]);
                uint32_t a3 = __float_as_uint(sX[(r0 + gid + 8) * SXP + kk * 8 + tg + 4]);
#pragma unroll
                for (int t = 0; t < 4; t++)
                    mma_tf32(c[mt][t], a0, a1, a2, a3, b[t][0], b[t][1]);
            }
        }
        __syncthreads();
    }

    // epilogue
#pragma unroll
    for (int mt = 0; mt < 4; mt++) {
        int r = rbase + mbase + mt * 16 + gid;
#pragma unroll
        for (int t = 0; t < 4; t++) {
            int col = t * 8 + 2 * tg;
            if (r < GN)
                *reinterpret_cast<float2*>(&g_xw[r * H0 + col]) =
                    make_float2(c[mt][t][0], c[mt][t][1]);
            if (r + 8 < GN)
                *reinterpret_cast<float2*>(&g_xw[(r + 8) * H0 + col]) =
                    make_float2(c[mt][t][2], c[mt][t][3]);
        }
    }
}

// ---------------- degree for conv1 (raw counts, no separate rsqrt pass) -----------
__global__ void k_deg1(const void* __restrict__ ei) {
    int e = blockIdx.x * blockDim.x + threadIdx.x;
    if (e >= GE) return;
    atomicAdd(&g_deg1[eidx(ei, (long long)GE + e)], 1.0f);
}

// ---------------- conv1 aggregation: 8 threads / edge, RED.128 ----------------
__global__ void k_agg1(const void* __restrict__ ei) {
    long long t = (long long)blockIdx.x * blockDim.x + threadIdx.x;
    if (t >= (long long)GE * 8) return;
    int e = (int)(t >> 3), q = (int)(t & 7);
    int row = eidx(ei, e);
    int col = eidx(ei, (long long)GE + e);
    float norm = rsqrtf(g_deg1[row] * g_deg1[col]);   // dinv_r * dinv_c
    float4 v = *reinterpret_cast<const float4*>(&g_xw[row * H0 + q * 4]);
    red4(&g_hacc[col * H0 + q * 4], v.x * norm, v.y * norm, v.z * norm, v.w * norm);
}

// ---------------- per-node: h, s1, s2, hw = h @ W1 (warp per node) ----------------
__global__ void k_node(const float* __restrict__ b0, const float* __restrict__ W1) {
    int node = (blockIdx.x * blockDim.x + threadIdx.x) >> 5;
    int lane = threadIdx.x & 31;
    if (node >= GN) return;

    float di2 = 1.0f / g_deg1[node];   // dinv1^2 for the self-loop term
    float h = g_hacc[node * H0 + lane] + g_xw[node * H0 + lane] * di2 + b0[lane];

    float p1 = h * g_wa1[lane];
    float p2 = h * g_wa2[lane];
#pragma unroll
    for (int o = 16; o; o >>= 1) {
        p1 += __shfl_xor_sync(0xFFFFFFFFu, p1, o);
        p2 += __shfl_xor_sync(0xFFFFFFFFu, p2, o);
    }
    if (lane == 0) { g_s1[node] = p1; g_s2[node] = p2; }

    float4 wA = *reinterpret_cast<const float4*>(W1 + lane * 8);
    float4 wB = *reinterpret_cast<const float4*>(W1 + lane * 8 + 4);
    float o0 = h * wA.x, o1 = h * wA.y, o2 = h * wA.z, o3 = h * wA.w;
    float o4 = h * wB.x, o5 = h * wB.y, o6 = h * wB.z, o7 = h * wB.w;
#pragma unroll
    for (int o = 16; o; o >>= 1) {
        o0 += __shfl_xor_sync(0xFFFFFFFFu, o0, o);
        o1 += __shfl_xor_sync(0xFFFFFFFFu, o1, o);
        o2 += __shfl_xor_sync(0xFFFFFFFFu, o2, o);
        o3 += __shfl_xor_sync(0xFFFFFFFFu, o3, o);
        o4 += __shfl_xor_sync(0xFFFFFFFFu, o4, o);
        o5 += __shfl_xor_sync(0xFFFFFFFFu, o5, o);
        o6 += __shfl_xor_sync(0xFFFFFFFFu, o6, o);
        o7 += __shfl_xor_sync(0xFFFFFFFFu, o7, o);
    }
    if (lane == 0) {
        float4* hw4 = reinterpret_cast<float4*>(&g_hw[node * H1]);
        hw4[0] = make_float4(o0, o1, o2, o3);
        hw4[1] = make_float4(o4, o5, o6, o7);
    }
}

// ---------------- edge gate + deg2 ----------------
__global__ void k_gate(const void* __restrict__ ei) {
    int e = blockIdx.x * blockDim.x + threadIdx.x;
    if (e >= GE) return;
    int row = eidx(ei, e);
    int col = eidx(ei, (long long)GE + e);
    float w = g_s1[row] + g_s2[col] + g_cbias;  // pre-relu attention logit
    float mw = 0.f;
    if (w > 0.f) {
        float s = 1.f / (1.f + __expf(-w));       // sigmoid(relu(w)), w>0
        float mask = fminf(s * 1.01f, 1.f);       // clip(s*(zeta-gamma)+gamma, 0, 1)
        mw = mask * w;
        atomicAdd(&g_deg2[col], mw);
    }
    g_mw[e] = mw;
}

// ---------------- rsq2 + g_out init (thread per node) ----------------
__global__ void k_oinit(const float* __restrict__ b1) {
    int node = blockIdx.x * blockDim.x + threadIdx.x;
    if (node >= GN) return;
    float d = rsqrtf(g_deg2[node]);
    g_deg2[node] = d;           // dinv2 for agg2
    float dd = d * d;
    float4 hw0 = *reinterpret_cast<const float4*>(&g_hw[node * H1]);
    float4 hw1 = *reinterpret_cast<const float4*>(&g_hw[node * H1 + 4]);
    float4 bA = *reinterpret_cast<const float4*>(b1);
    float4 bB = *reinterpret_cast<const float4*>(b1 + 4);
    float4 o0 = make_float4(hw0.x * dd + bA.x, hw0.y * dd + bA.y,
                            hw0.z * dd + bA.z, hw0.w * dd + bA.w);
    float4 o1 = make_float4(hw1.x * dd + bB.x, hw1.y * dd + bB.y,
                            hw1.z * dd + bB.z, hw1.w * dd + bB.w);
    *reinterpret_cast<float4*>(&g_out[node * H1]) = o0;
    *reinterpret_cast<float4*>(&g_out[node * H1 + 4]) = o1;
}

// ---------------- conv2 aggregation: 2 threads / edge, RED.128 ----------------
__global__ void k_agg2(const void* __restrict__ ei) {
    long long t = (long long)blockIdx.x * blockDim.x + threadIdx.x;
    if (t >= (long long)GE * 2) return;
    int e = (int)(t >> 1), q = (int)(t & 1);
    float mw = g_mw[e];
    if (mw == 0.f) return;  // gated off: exact zero contribution
    int row = eidx(ei, e);
    int col = eidx(ei, (long long)GE + e);
    float norm = g_deg2[row] * mw * g_deg2[col];
    float4 v = *reinterpret_cast<const float4*>(&g_hw[row * H1 + q * 4]);
    red4(&g_out[col * H1 + q * 4], v.x * norm, v.y * norm, v.z * norm, v.w * norm);
}

// ---------------- final copy ----------------
__global__ void k_final(float* __restrict__ out) {
    int i = blockIdx.x * blockDim.x + threadIdx.x;
    if (i < GN * H1 / 4) {
        reinterpret_cast<float4*>(out)[i] = reinterpret_cast<const float4*>(g_out)[i];
    }
}

// ---------------- launch ----------------
extern "C" void kernel_launch(void* const* d_in, const int* in_sizes, int n_in,
                              void* d_out, int out_size) {
    const float* x   = (const float*)d_in[0];
    const void*  ei  = d_in[1];
    const float* W0  = (const float*)d_in[2];
    const float* b0  = (const float*)d_in[3];
    const float* W1  = (const float*)d_in[4];
    const float* b1  = (const float*)d_in[5];
    const float* Wnb = (const float*)d_in[6];
    const float* bnb = (const float*)d_in[7];
    const float* Wself = (const float*)d_in[8];
    const float* bself = (const float*)d_in[9];
    const float* Watt  = (const float*)d_in[10];
    const float* batt  = (const float*)d_in[11];
    float* out = (float*)d_out;

    k_setup<<<(GN * H0 + 255) / 256, 256>>>((const unsigned int*)ei,
                                            Wnb, bnb, Wself, bself, Watt, batt);
    k_gemm<<<(GN + 255) / 256, 128>>>(x, W0);
    k_deg1<<<(GE + 255) / 256, 256>>>(ei);
    k_agg1<<<(GE * 8 + 255) / 256, 256>>>(ei);
    k_node<<<(GN * 32 + 255) / 256, 256>>>(b0, W1);
    k_gate<<<(GE + 255) / 256, 256>>>(ei);
    k_oinit<<<(GN + 255) / 256, 256>>>(b1);
    k_agg2<<<(GE * 2 + 255) / 256, 256>>>(ei);
    k_final<<<(GN * H1 / 4 + 255) / 256, 256>>>(out);
}

// round 11
// speedup vs baseline: 1.4888x; 1.0411x over previous
#include <cuda_runtime.h>
#include <cstdint>

#define GN 100000
#define GE 1600000
#define H0 32
#define H1 8

// ---------------- scratch (static __device__ — no allocations) ----------------
__device__ __align__(16) float g_xw[GN * H0];    // x @ W0
__device__ __align__(16) float g_hacc[GN * H0];  // conv1 edge aggregation
__device__ __align__(16) float g_out[GN * H1];   // conv2 aggregation (no atomics on d_out)
__device__ __align__(16) float g_hw[GN * H1];    // h @ W1
__device__ __align__(16) int2  g_eidx[GE];       // packed (row, col) int32
__device__ float g_deg1[GN];       // raw degree (1 + count)
__device__ float g_deg2[GN];       // masked-weight degree -> dinv2 (in place)
__device__ float g_s1[GN];
__device__ float g_s2[GN];
__device__ float g_mw[GE];         // masked edge weight
__device__ float g_wa1[H0];
__device__ float g_wa2[H0];
__device__ float g_cbias;
__device__ int   g_is64;

// ---------------- helpers ----------------
__device__ __forceinline__ void red4(float* a, float x, float y, float z, float w) {
    asm volatile(
        "{\n\t"
        ".reg .u64 p;\n\t"
        "cvta.to.global.u64 p, %0;\n\t"
        "red.global.add.v4.f32 [p], {%1,%2,%3,%4};\n\t"
        "}"
        :: "l"(a), "f"(x), "f"(y), "f"(z), "f"(w) : "memory");
}

__device__ __forceinline__ int eidx(const void* ei, long long i) {
    if (g_is64) return (int)((const long long*)ei)[i];
    return ((const int*)ei)[i];
}

__device__ __forceinline__ float tf32r(float a) {
    float r;
    asm("cvt.rna.tf32.f32 %0, %1;" : "=f"(r) : "f"(a));
    return r;
}

__device__ __forceinline__ void mma_tf32(float* c, uint32_t a0, uint32_t a1,
                                         uint32_t a2, uint32_t a3,
                                         uint32_t b0, uint32_t b1) {
    asm("mma.sync.aligned.m16n8k8.row.col.f32.tf32.tf32.f32 "
        "{%0,%1,%2,%3},{%4,%5,%6,%7},{%8,%9},{%0,%1,%2,%3};"
        : "+f"(c[0]), "+f"(c[1]), "+f"(c[2]), "+f"(c[3])
        : "r"(a0), "r"(a1), "r"(a2), "r"(a3), "r"(b0), "r"(b1));
}

// ---------------- fused setup ----------------
__global__ void k_setup(const unsigned int* __restrict__ eiw,
                        const float* __restrict__ Wnb, const float* __restrict__ bnb,
                        const float* __restrict__ Wself, const float* __restrict__ bself,
                        const float* __restrict__ Watt, const float* __restrict__ batt) {
    int i = blockIdx.x * blockDim.x + threadIdx.x;
    if (i < GN * H0) g_hacc[i] = 0.f;
    if (i < GN) { g_deg1[i] = 1.f; g_deg2[i] = 1.f; }  // self-loop weight 1
    if (i < H0) {
        float a1 = 0.f, a2 = 0.f;
#pragma unroll
        for (int k = 0; k < 8; k++) {
            a1 += Wnb[i * 8 + k] * Watt[k];
            a2 += Wself[i * 8 + k] * Watt[8 + k];
        }
        g_wa1[i] = a1;
        g_wa2[i] = a2;
    }
    if (i == H0) {
        float c = batt[0];
        for (int k = 0; k < 8; k++) c += bnb[k] * Watt[k] + bself[k] * Watt[8 + k];
        g_cbias = c;
    }
    if (i == H0 + 1) {
        // edge values < 2^17: if int64 (LE), every odd 32-bit word is 0
        int all0 = 1;
        for (int j = 1; j < 512; j += 2)
            if (eiw[j] != 0u) { all0 = 0; break; }
        g_is64 = all0;
    }
}

// ---------------- GEMM: xw = x @ W0, tf32 tensor cores ----------------
#define SXP 36
#define SWP 33
__global__ __launch_bounds__(128) void k_gemm(const float* __restrict__ x,
                                              const float* __restrict__ W0) {
    __shared__ __align__(16) float sX[256 * SXP];  // 36.9KB (tf32-rounded)
    __shared__ __align__(16) float sW[32 * SWP];   // 4.2KB

    const int tid = threadIdx.x;
    const int lane = tid & 31;
    const int gid = lane >> 2;
    const int tg = lane & 3;
    const int mbase = (tid >> 5) * 64;
    const int rbase = blockIdx.x * 256;

    float c[4][4][4];
#pragma unroll
    for (int mt = 0; mt < 4; mt++)
#pragma unroll
        for (int t = 0; t < 4; t++)
#pragma unroll
            for (int r = 0; r < 4; r++) c[mt][t][r] = 0.f;

    for (int k0 = 0; k0 < 512; k0 += 32) {
#pragma unroll
        for (int i = 0; i < 16; i++) {
            int idx = tid + 128 * i;
            int row = idx >> 3, q = idx & 7;
            int grow = rbase + row;
            if (grow >= GN) grow = GN - 1;
            float4 v = *reinterpret_cast<const float4*>(
                x + (size_t)grow * 512 + k0 + 4 * q);
            v.x = tf32r(v.x); v.y = tf32r(v.y); v.z = tf32r(v.z); v.w = tf32r(v.w);
            *reinterpret_cast<float4*>(&sX[row * SXP + 4 * q]) = v;
        }
#pragma unroll
        for (int i = 0; i < 8; i++) {
            int idx = tid + 128 * i;
            int kk = idx >> 5, cc = idx & 31;
            sW[kk * SWP + cc] = tf32r(W0[(k0 + kk) * H0 + cc]);
        }
        __syncthreads();

#pragma unroll
        for (int kk = 0; kk < 4; kk++) {
            uint32_t b[4][2];
#pragma unroll
            for (int t = 0; t < 4; t++) {
                b[t][0] = __float_as_uint(sW[(kk * 8 + tg) * SWP + t * 8 + gid]);
                b[t][1] = __float_as_uint(sW[(kk * 8 + tg + 4) * SWP + t * 8 + gid]);
            }
#pragma unroll
            for (int mt = 0; mt < 4; mt++) {
                int r0 = mbase + mt * 16;
                uint32_t a0 = __float_as_uint(sX[(r0 + gid) * SXP + kk * 8 + tg]);
                uint32_t a1 = __float_as_uint(sX[(r0 + gid + 8) * SXP + kk * 8 + tg]);
                uint32_t a2 = __float_as_uint(sX[(r0 + gid) * SXP + kk * 8 + tg + 4]);
                uint32_t a3 = __float_as_uint(sX[(r0 + gid + 8) * SXP + kk * 8 + tg + 4]);
#pragma unroll
                for (int t = 0; t < 4; t++)
                    mma_tf32(c[mt][t], a0, a1, a2, a3, b[t][0], b[t][1]);
            }
        }
        __syncthreads();
    }

#pragma unroll
    for (int mt = 0; mt < 4; mt++) {
        int r = rbase + mbase + mt * 16 + gid;
#pragma unroll
        for (int t = 0; t < 4; t++) {
            int col = t * 8 + 2 * tg;
            if (r < GN)
                *reinterpret_cast<float2*>(&g_xw[r * H0 + col]) =
                    make_float2(c[mt][t][0], c[mt][t][1]);
            if (r + 8 < GN)
                *reinterpret_cast<float2*>(&g_xw[(r + 8) * H0 + col]) =
                    make_float2(c[mt][t][2], c[mt][t][3]);
        }
    }
}

// ---------------- edge conversion to packed int2 + degree histogram ----------------
__global__ void k_cvtdeg(const void* __restrict__ ei) {
    int e = blockIdx.x * blockDim.x + threadIdx.x;
    if (e >= GE) return;
    int r = eidx(ei, e);
    int c = eidx(ei, (long long)GE + e);
    g_eidx[e] = make_int2(r, c);
    atomicAdd(&g_deg1[c], 1.0f);
}

// ---------------- conv1 aggregation: 8 lanes/edge, scalar work deduped ------------
__global__ __launch_bounds__(256) void k_agg1() {
    long long t = (long long)blockIdx.x * blockDim.x + threadIdx.x;
    if (t >= (long long)GE * 8) return;
    int e = (int)(t >> 3);
    int sub = (int)(t & 7);
    int lane = threadIdx.x & 31;
    int lead = lane & ~7;          // first lane of this 8-lane group

    int row = 0, col = 0;
    float norm = 0.f;
    if ((lane & 7) == 0) {
        int2 rc = g_eidx[e];
        row = rc.x; col = rc.y;
        norm = rsqrtf(g_deg1[row] * g_deg1[col]);
    }
    row  = __shfl_sync(0xFFFFFFFFu, row, lead);
    col  = __shfl_sync(0xFFFFFFFFu, col, lead);
    norm = __shfl_sync(0xFFFFFFFFu, norm, lead);

    float4 v = *reinterpret_cast<const float4*>(&g_xw[row * H0 + sub * 4]);
    red4(&g_hacc[col * H0 + sub * 4], v.x * norm, v.y * norm, v.z * norm, v.w * norm);
}

// ---------------- per-node: h, s1, s2, hw = h @ W1 (warp per node) ----------------
__global__ void k_node(const float* __restrict__ b0, const float* __restrict__ W1) {
    int node = (blockIdx.x * blockDim.x + threadIdx.x) >> 5;
    int lane = threadIdx.x & 31;
    if (node >= GN) return;

    float di2 = 1.0f / g_deg1[node];   // dinv1^2 for the self-loop term
    float h = g_hacc[node * H0 + lane] + g_xw[node * H0 + lane] * di2 + b0[lane];

    float p1 = h * g_wa1[lane];
    float p2 = h * g_wa2[lane];
#pragma unroll
    for (int o = 16; o; o >>= 1) {
        p1 += __shfl_xor_sync(0xFFFFFFFFu, p1, o);
        p2 += __shfl_xor_sync(0xFFFFFFFFu, p2, o);
    }
    if (lane == 0) { g_s1[node] = p1; g_s2[node] = p2; }

    float4 wA = *reinterpret_cast<const float4*>(W1 + lane * 8);
    float4 wB = *reinterpret_cast<const float4*>(W1 + lane * 8 + 4);
    float o0 = h * wA.x, o1 = h * wA.y, o2 = h * wA.z, o3 = h * wA.w;
    float o4 = h * wB.x, o5 = h * wB.y, o6 = h * wB.z, o7 = h * wB.w;
#pragma unroll
    for (int o = 16; o; o >>= 1) {
        o0 += __shfl_xor_sync(0xFFFFFFFFu, o0, o);
        o1 += __shfl_xor_sync(0xFFFFFFFFu, o1, o);
        o2 += __shfl_xor_sync(0xFFFFFFFFu, o2, o);
        o3 += __shfl_xor_sync(0xFFFFFFFFu, o3, o);
        o4 += __shfl_xor_sync(0xFFFFFFFFu, o4, o);
        o5 += __shfl_xor_sync(0xFFFFFFFFu, o5, o);
        o6 += __shfl_xor_sync(0xFFFFFFFFu, o6, o);
        o7 += __shfl_xor_sync(0xFFFFFFFFu, o7, o);
    }
    if (lane == 0) {
        float4* hw4 = reinterpret_cast<float4*>(&g_hw[node * H1]);
        hw4[0] = make_float4(o0, o1, o2, o3);
        hw4[1] = make_float4(o4, o5, o6, o7);
    }
}

// ---------------- edge gate + deg2 ----------------
__global__ void k_gate() {
    int e = blockIdx.x * blockDim.x + threadIdx.x;
    if (e >= GE) return;
    int2 rc = g_eidx[e];
    float w = g_s1[rc.x] + g_s2[rc.y] + g_cbias;  // pre-relu attention logit
    float mw = 0.f;
    if (w > 0.f) {
        float s = 1.f / (1.f + __expf(-w));       // sigmoid(relu(w)), w>0
        float mask = fminf(s * 1.01f, 1.f);       // clip(s*(zeta-gamma)+gamma, 0, 1)
        mw = mask * w;
        atomicAdd(&g_deg2[rc.y], mw);
    }
    g_mw[e] = mw;
}

// ---------------- rsq2 + g_out init (thread per node) ----------------
__global__ void k_oinit(const float* __restrict__ b1) {
    int node = blockIdx.x * blockDim.x + threadIdx.x;
    if (node >= GN) return;
    float d = rsqrtf(g_deg2[node]);
    g_deg2[node] = d;           // dinv2 for agg2
    float dd = d * d;
    float4 hw0 = *reinterpret_cast<const float4*>(&g_hw[node * H1]);
    float4 hw1 = *reinterpret_cast<const float4*>(&g_hw[node * H1 + 4]);
    float4 bA = *reinterpret_cast<const float4*>(b1);
    float4 bB = *reinterpret_cast<const float4*>(b1 + 4);
    float4 o0 = make_float4(hw0.x * dd + bA.x, hw0.y * dd + bA.y,
                            hw0.z * dd + bA.z, hw0.w * dd + bA.w);
    float4 o1 = make_float4(hw1.x * dd + bB.x, hw1.y * dd + bB.y,
                            hw1.z * dd + bB.z, hw1.w * dd + bB.w);
    *reinterpret_cast<float4*>(&g_out[node * H1]) = o0;
    *reinterpret_cast<float4*>(&g_out[node * H1 + 4]) = o1;
}

// ---------------- conv2 aggregation: 2 threads / edge, RED.128 ----------------
__global__ void k_agg2() {
    long long t = (long long)blockIdx.x * blockDim.x + threadIdx.x;
    if (t >= (long long)GE * 2) return;
    int e = (int)(t >> 1), q = (int)(t & 1);
    float mw = g_mw[e];
    if (mw == 0.f) return;  // gated off: exact zero contribution
    int2 rc = g_eidx[e];
    float norm = g_deg2[rc.x] * mw * g_deg2[rc.y];
    float4 v = *reinterpret_cast<const float4*>(&g_hw[rc.x * H1 + q * 4]);
    red4(&g_out[rc.y * H1 + q * 4], v.x * norm, v.y * norm, v.z * norm, v.w * norm);
}

// ---------------- final copy ----------------
__global__ void k_final(float* __restrict__ out) {
    int i = blockIdx.x * blockDim.x + threadIdx.x;
    if (i < GN * H1 / 4) {
        reinterpret_cast<float4*>(out)[i] = reinterpret_cast<const float4*>(g_out)[i];
    }
}

// ---------------- launch ----------------
extern "C" void kernel_launch(void* const* d_in, const int* in_sizes, int n_in,
                              void* d_out, int out_size) {
    const float* x   = (const float*)d_in[0];
    const void*  ei  = d_in[1];
    const float* W0  = (const float*)d_in[2];
    const float* b0  = (const float*)d_in[3];
    const float* W1  = (const float*)d_in[4];
    const float* b1  = (const float*)d_in[5];
    const float* Wnb = (const float*)d_in[6];
    const float* bnb = (const float*)d_in[7];
    const float* Wself = (const float*)d_in[8];
    const float* bself = (const float*)d_in[9];
    const float* Watt  = (const float*)d_in[10];
    const float* batt  = (const float*)d_in[11];
    float* out = (float*)d_out;

    k_setup<<<(GN * H0 + 255) / 256, 256>>>((const unsigned int*)ei,
                                            Wnb, bnb, Wself, bself, Watt, batt);
    k_gemm<<<(GN + 255) / 256, 128>>>(x, W0);
    k_cvtdeg<<<(GE + 255) / 256, 256>>>(ei);
    k_agg1<<<(GE * 8 + 255) / 256, 256>>>();
    k_node<<<(GN * 32 + 255) / 256, 256>>>(b0, W1);
    k_gate<<<(GE + 255) / 256, 256>>>();
    k_oinit<<<(GN + 255) / 256, 256>>>(b1);
    k_agg2<<<(GE * 2 + 255) / 256, 256>>>();
    k_final<<<(GN * H1 / 4 + 255) / 256, 256>>>(out);
}